// round 1
// baseline (speedup 1.0000x reference)
#include <cuda_runtime.h>
#include <cstdint>

// Problem constants
#define BB 4
#define PP 2048
#define EE 4096
#define SS 16

// Scratch: precomputed projections
__device__ float g_pa[PP * SS];   // product @ Wa   [p][s]
__device__ float g_pb[EE * SS];   // person  @ Wb   [e][s]

// ---------------- packed f32x2 helpers ----------------
__device__ __forceinline__ unsigned long long pack2(float lo, float hi) {
    unsigned long long r;
    asm("mov.b64 %0, {%1, %2};" : "=l"(r) : "f"(lo), "f"(hi));
    return r;
}
__device__ __forceinline__ void unpack2(unsigned long long v, float& lo, float& hi) {
    asm("mov.b64 {%0, %1}, %2;" : "=f"(lo), "=f"(hi) : "l"(v));
}
__device__ __forceinline__ unsigned long long fma2(unsigned long long a,
                                                   unsigned long long b,
                                                   unsigned long long c) {
    unsigned long long d;
    asm("fma.rn.f32x2 %0, %1, %2, %3;" : "=l"(d) : "l"(a), "l"(b), "l"(c));
    return d;
}

// Accurate tanh: 1 - 2/(exp(2x)+1), via ex2.approx (rel err ~2^-22) and
// rcp.approx. Inputs here are bounded |x| < ~0.9, well inside safe range.
__device__ __forceinline__ float tanh_acc(float x) {
    float e;
    asm("ex2.approx.f32 %0, %1;" : "=f"(e) : "f"(x * 2.885390081777927f)); // 2*log2(e)
    float r;
    asm("rcp.approx.f32 %0, %1;" : "=f"(r) : "f"(e + 1.0f));
    return fmaf(-2.0f, r, 1.0f);
}

// ---------------- kernel 1: tiny projections ----------------
__global__ void prep_kernel(const float* __restrict__ product,
                            const float* __restrict__ person,
                            const float* __restrict__ W1) {
    int idx = blockIdx.x * blockDim.x + threadIdx.x;
    const int total = (PP + EE) * SS;
    if (idx >= total) return;
    int row = idx >> 4;
    int j = idx & 15;
    if (row < PP) {
        float acc = 0.f;
#pragma unroll
        for (int s = 0; s < SS; s++)
            acc = fmaf(product[row * SS + s], W1[s * SS + j], acc);
        g_pa[idx] = acc;
    } else {
        int e = row - PP;
        float acc = 0.f;
#pragma unroll
        for (int s = 0; s < SS; s++)
            acc = fmaf(person[e * SS + s], W1[(SS + s) * SS + j], acc);
        g_pb[e * SS + j] = acc;
    }
}

// ---------------- kernel 2: fused score + broadcast multiply ----------------
// grid: (EE/512, PP), block: 128 threads. Each thread handles 4 e's:
//   e_k = blockIdx.x*512 + k*128 + tid   (k = 0..3) -> coalesced x/out access.
// f32x2 packs (k0,k1) and (k2,k3).
__global__ __launch_bounds__(128)
void adjacency_main(const float* __restrict__ x,
                    const float* __restrict__ W2,
                    const float* __restrict__ W3,
                    float* __restrict__ out) {
    __shared__ float2 w2d[SS * SS];  // duplicated weights {w,w}, [s][j]
    __shared__ float u_sm[SS];
    __shared__ float w3_sm[SS];

    const int tid = threadIdx.x;
    const int p = blockIdx.y;

    for (int i = tid; i < SS * SS; i += 128) {
        float w = W2[i];
        w2d[i] = make_float2(w, w);
    }
    if (tid < SS) {
        u_sm[tid] = g_pa[p * SS + tid];
        w3_sm[tid] = W3[tid];
    }
    __syncthreads();

    const int e0 = blockIdx.x * 512 + tid;
    const int e1 = e0 + 128;
    const int e2 = e0 + 256;
    const int e3 = e0 + 384;

    const float4* __restrict__ pb4 = reinterpret_cast<const float4*>(g_pb);

    // ---- h1 = tanh(u + v), packed over e-pairs ----
    unsigned long long h1a[SS];  // lanes (e0, e1)
    unsigned long long h1b[SS];  // lanes (e2, e3)
#pragma unroll
    for (int q = 0; q < 4; q++) {
        float4 v0 = pb4[e0 * 4 + q];
        float4 v1 = pb4[e1 * 4 + q];
        float4 v2 = pb4[e2 * 4 + q];
        float4 v3 = pb4[e3 * 4 + q];
        float u0 = u_sm[4 * q + 0];
        float u1 = u_sm[4 * q + 1];
        float u2 = u_sm[4 * q + 2];
        float u3 = u_sm[4 * q + 3];
        h1a[4 * q + 0] = pack2(tanh_acc(u0 + v0.x), tanh_acc(u0 + v1.x));
        h1b[4 * q + 0] = pack2(tanh_acc(u0 + v2.x), tanh_acc(u0 + v3.x));
        h1a[4 * q + 1] = pack2(tanh_acc(u1 + v0.y), tanh_acc(u1 + v1.y));
        h1b[4 * q + 1] = pack2(tanh_acc(u1 + v2.y), tanh_acc(u1 + v3.y));
        h1a[4 * q + 2] = pack2(tanh_acc(u2 + v0.z), tanh_acc(u2 + v1.z));
        h1b[4 * q + 2] = pack2(tanh_acc(u2 + v2.z), tanh_acc(u2 + v3.z));
        h1a[4 * q + 3] = pack2(tanh_acc(u3 + v0.w), tanh_acc(u3 + v1.w));
        h1b[4 * q + 3] = pack2(tanh_acc(u3 + v2.w), tanh_acc(u3 + v3.w));
    }

    // ---- h2 = tanh(h1 @ W2); z = h2 @ W3 (j-chunked to cap registers) ----
    const unsigned long long* __restrict__ w2u =
        reinterpret_cast<const unsigned long long*>(w2d);

    float z0 = 0.f, z1 = 0.f, z2 = 0.f, z3 = 0.f;
#pragma unroll
    for (int jc = 0; jc < 4; jc++) {
        unsigned long long accA[4], accB[4];
#pragma unroll
        for (int jj = 0; jj < 4; jj++) { accA[jj] = 0ull; accB[jj] = 0ull; }
#pragma unroll
        for (int s = 0; s < SS; s++) {
#pragma unroll
            for (int jj = 0; jj < 4; jj++) {
                unsigned long long w = w2u[s * SS + jc * 4 + jj];
                accA[jj] = fma2(h1a[s], w, accA[jj]);
                accB[jj] = fma2(h1b[s], w, accB[jj]);
            }
        }
#pragma unroll
        for (int jj = 0; jj < 4; jj++) {
            int j = jc * 4 + jj;
            float w3j = w3_sm[j];
            float a, b;
            unpack2(accA[jj], a, b);
            z0 = fmaf(tanh_acc(a), w3j, z0);
            z1 = fmaf(tanh_acc(b), w3j, z1);
            unpack2(accB[jj], a, b);
            z2 = fmaf(tanh_acc(a), w3j, z2);
            z3 = fmaf(tanh_acc(b), w3j, z3);
        }
    }

    // ---- leaky relu ----
    float sc0 = z0 >= 0.f ? z0 : 0.1f * z0;
    float sc1 = z1 >= 0.f ? z1 : 0.1f * z1;
    float sc2 = z2 >= 0.f ? z2 : 0.1f * z2;
    float sc3 = z3 >= 0.f ? z3 : 0.1f * z3;

    // ---- out[b,p,e] = score * x[b,p,e] for all 4 batches ----
#pragma unroll
    for (int b = 0; b < BB; b++) {
        unsigned base = ((unsigned)b * PP + p) * EE;
        out[base + e0] = sc0 * x[base + e0];
        out[base + e1] = sc1 * x[base + e1];
        out[base + e2] = sc2 * x[base + e2];
        out[base + e3] = sc3 * x[base + e3];
    }
}

extern "C" void kernel_launch(void* const* d_in, const int* in_sizes, int n_in,
                              void* d_out, int out_size) {
    const float* x       = (const float*)d_in[0];
    const float* product = (const float*)d_in[1];
    const float* person  = (const float*)d_in[2];
    const float* W1      = (const float*)d_in[3];
    const float* W2      = (const float*)d_in[4];
    const float* W3      = (const float*)d_in[5];
    float* out = (float*)d_out;

    {
        int total = (PP + EE) * SS;
        int threads = 256;
        int blocks = (total + threads - 1) / threads;
        prep_kernel<<<blocks, threads>>>(product, person, W1);
    }
    {
        dim3 grid(EE / 512, PP);
        adjacency_main<<<grid, 128>>>(x, W2, W3, out);
    }
}